// round 2
// baseline (speedup 1.0000x reference)
#include <cuda_runtime.h>
#include <cuda_bf16.h>
#include <cstdint>

// Problem constants (fixed shapes)
#define B_   32
#define T_   8
#define LL   197
#define CC   768
#define CAd  384
#define BTd  256            // B_*T_
#define MM   50176          // BTd*196

// Scratch (device globals — no allocation allowed)
__device__ __align__(256) __nv_bfloat16 g_xb[(size_t)MM * CC];   // x without CLS, bf16
__device__ __align__(256) __nv_bfloat16 g_h1[(size_t)MM * CAd];
__device__ __align__(256) __nv_bfloat16 g_h2[(size_t)MM * CAd];
__device__ __align__(256) __nv_bfloat16 g_w1[CAd * CC];
__device__ __align__(256) __nv_bfloat16 g_w2[CC * CAd];

// ---------------------------------------------------------------------------
// prep: weights -> bf16, x(non-CLS) -> bf16 packed [MM, CC], copy CLS rows
// ---------------------------------------------------------------------------
__global__ void prep_kernel(const float* __restrict__ W1, const float* __restrict__ W2,
                            const float* __restrict__ x, float* __restrict__ out) {
    int stride = gridDim.x * blockDim.x;
    int i0 = blockIdx.x * blockDim.x + threadIdx.x;

    // weights (vectorized float4 -> 2x bf16x2)
    for (int i = i0; i < (CAd * CC) / 4; i += stride) {
        float4 v = ((const float4*)W1)[i];
        __nv_bfloat162 p0 = __floats2bfloat162_rn(v.x, v.y);
        __nv_bfloat162 p1 = __floats2bfloat162_rn(v.z, v.w);
        uint2 u; u.x = *(uint32_t*)&p0; u.y = *(uint32_t*)&p1;
        ((uint2*)g_w1)[i] = u;
    }
    for (int i = i0; i < (CAd * CC) / 4; i += stride) {
        float4 v = ((const float4*)W2)[i];
        __nv_bfloat162 p0 = __floats2bfloat162_rn(v.x, v.y);
        __nv_bfloat162 p1 = __floats2bfloat162_rn(v.z, v.w);
        uint2 u; u.x = *(uint32_t*)&p0; u.y = *(uint32_t*)&p1;
        ((uint2*)g_w2)[i] = u;
    }
    // x non-CLS tokens -> bf16 packed
    const int R4 = CC / 4;  // 192
    for (int i = i0; i < MM * R4; i += stride) {
        int m = i / R4;
        int c4 = i - m * R4;
        int xr = m + m / 196 + 1;
        float4 v = *(const float4*)(x + (size_t)xr * CC + c4 * 4);
        __nv_bfloat162 p0 = __floats2bfloat162_rn(v.x, v.y);
        __nv_bfloat162 p1 = __floats2bfloat162_rn(v.z, v.w);
        uint2 u; u.x = *(uint32_t*)&p0; u.y = *(uint32_t*)&p1;
        ((uint2*)g_xb)[(size_t)m * R4 + c4] = u;
    }
    // CLS rows copy x -> out
    for (int i = i0; i < (BTd * CC) / 4; i += stride) {
        int bt = i / (CC / 4), c4 = i - bt * (CC / 4);
        size_t off = (size_t)bt * LL * (CC / 4) + c4;
        ((float4*)out)[off] = ((const float4*)x)[off];
    }
}

// ---------------------------------------------------------------------------
// GEMM helpers (mma.sync m16n8k16 bf16 + cp.async staging)
// ---------------------------------------------------------------------------
__device__ __forceinline__ uint32_t smem_u32(const void* p) {
    return (uint32_t)__cvta_generic_to_shared(p);
}
__device__ __forceinline__ void ldm_x4(uint32_t* r, uint32_t addr) {
    asm volatile("ldmatrix.sync.aligned.m8n8.x4.shared.b16 {%0,%1,%2,%3}, [%4];\n"
                 : "=r"(r[0]), "=r"(r[1]), "=r"(r[2]), "=r"(r[3]) : "r"(addr));
}
__device__ __forceinline__ void mma_bf16(float* d, const uint32_t* a, uint32_t b0, uint32_t b1) {
    asm volatile(
        "mma.sync.aligned.m16n8k16.row.col.f32.bf16.bf16.f32 "
        "{%0,%1,%2,%3}, {%4,%5,%6,%7}, {%8,%9}, {%0,%1,%2,%3};\n"
        : "+f"(d[0]), "+f"(d[1]), "+f"(d[2]), "+f"(d[3])
        : "r"(a[0]), "r"(a[1]), "r"(a[2]), "r"(a[3]), "r"(b0), "r"(b1));
}
__device__ __forceinline__ void cp16(void* smem, const void* gmem) {
    uint32_t s = smem_u32(smem);
    asm volatile("cp.async.cg.shared.global [%0], [%1], 16;\n" :: "r"(s), "l"(gmem));
}
#define CP_COMMIT asm volatile("cp.async.commit_group;\n" ::: "memory")
#define CP_WAIT0  asm volatile("cp.async.wait_group 0;\n" ::: "memory")

#define SK 40   // smem row stride (32 + 8 pad) -> 80B, ldmatrix conflict-free
#define STG (128 * SK)

// Shared GEMM mainloop: C[128x128] tile of A[M,K] * B[N,K]^T, both bf16 row-major.
// 2-stage cp.async pipeline, issue-early. 8 warps as 4(M)x2(N), warp tile 32x64.
template<int K>
__device__ __forceinline__ void gemm_loop(const __nv_bfloat16* __restrict__ A,
                                          const __nv_bfloat16* __restrict__ B,
                                          __nv_bfloat16* As, __nv_bfloat16* Bs,
                                          int bm, int bn, float (&acc)[2][8][4]) {
    const int tid = threadIdx.x;
    const int row = tid >> 2;          // 0..63
    const int col = (tid & 3) * 8;     // element offset (16B chunk)
    const __nv_bfloat16* aptr[2] = {
        A + (size_t)(bm + row) * K + col,
        A + (size_t)(bm + row + 64) * K + col };
    const __nv_bfloat16* bptr[2] = {
        B + (size_t)(bn + row) * K + col,
        B + (size_t)(bn + row + 64) * K + col };

    const int lane = tid & 31, warp = tid >> 5;
    const int wm = (warp & 3) * 32, wn = (warp >> 2) * 64;
    const int lr = ((lane >> 3) & 1) * 8 + (lane & 7);
    const int kc = (lane >> 4) * 8;

#pragma unroll
    for (int i = 0; i < 2; i++)
#pragma unroll
        for (int j = 0; j < 8; j++)
#pragma unroll
            for (int c = 0; c < 4; c++) acc[i][j][c] = 0.f;

    // stage 0 loads
#pragma unroll
    for (int p = 0; p < 2; p++) {
        cp16(&As[(row + p * 64) * SK + col], aptr[p]);
        cp16(&Bs[(row + p * 64) * SK + col], bptr[p]);
    }
    CP_COMMIT;

    const int nk = K / 32;
#pragma unroll 1
    for (int kt = 0; kt < nk; kt++) {
        CP_WAIT0;
        __syncthreads();
        // issue next stage early: overlaps with this tile's compute
        if (kt + 1 < nk) {
            int off = (kt + 1) * 32;
            __nv_bfloat16* An = As + ((kt + 1) & 1) * STG;
            __nv_bfloat16* Bn = Bs + ((kt + 1) & 1) * STG;
#pragma unroll
            for (int p = 0; p < 2; p++) {
                cp16(&An[(row + p * 64) * SK + col], aptr[p] + off);
                cp16(&Bn[(row + p * 64) * SK + col], bptr[p] + off);
            }
        }
        CP_COMMIT;

        uint32_t a_s = smem_u32(As + (kt & 1) * STG);
        uint32_t b_s = smem_u32(Bs + (kt & 1) * STG);
#pragma unroll
        for (int ks = 0; ks < 32; ks += 16) {
            uint32_t ra[2][4], rb[4][4];
#pragma unroll
            for (int i = 0; i < 2; i++)
                ldm_x4(ra[i], a_s + (uint32_t)(((wm + i * 16 + lr) * SK + ks + kc) * 2));
#pragma unroll
            for (int j = 0; j < 4; j++)
                ldm_x4(rb[j], b_s + (uint32_t)(((wn + j * 16 + lr) * SK + ks + kc) * 2));
#pragma unroll
            for (int i = 0; i < 2; i++)
#pragma unroll
                for (int j = 0; j < 4; j++) {
                    mma_bf16(acc[i][2 * j],     ra[i], rb[j][0], rb[j][2]);
                    mma_bf16(acc[i][2 * j + 1], ra[i], rb[j][1], rb[j][3]);
                }
        }
        __syncthreads();
    }
}

// ---------------------------------------------------------------------------
// fc1: h1 = xb @ W1^T + b1   (M=50176, N=384, K=768), out bf16
// ---------------------------------------------------------------------------
__global__ __launch_bounds__(256) void fc1_kernel(const float* __restrict__ b1) {
    __shared__ __align__(16) __nv_bfloat16 As[2 * STG];
    __shared__ __align__(16) __nv_bfloat16 Bs[2 * STG];
    const int bm = blockIdx.y * 128;
    const int bn = blockIdx.x * 128;
    float acc[2][8][4];
    gemm_loop<CC>(g_xb, g_w1, As, Bs, bm, bn, acc);

    const int lane = threadIdx.x & 31, warp = threadIdx.x >> 5;
    const int wm = (warp & 3) * 32, wn = (warp >> 2) * 64;
    const int lane4 = lane & 3, laneg = lane >> 2;
    uint32_t* h1w = (uint32_t*)g_h1;
#pragma unroll
    for (int i = 0; i < 2; i++) {
#pragma unroll
        for (int jj = 0; jj < 8; jj++) {
            int n = bn + wn + jj * 8 + lane4 * 2;
            float bx = b1[n], by = b1[n + 1];
            int m0 = bm + wm + i * 16 + laneg;
            __nv_bfloat162 v0 = __floats2bfloat162_rn(acc[i][jj][0] + bx, acc[i][jj][1] + by);
            h1w[(size_t)m0 * (CAd / 2) + (n >> 1)] = *(uint32_t*)&v0;
            __nv_bfloat162 v1 = __floats2bfloat162_rn(acc[i][jj][2] + bx, acc[i][jj][3] + by);
            h1w[(size_t)(m0 + 8) * (CAd / 2) + (n >> 1)] = *(uint32_t*)&v1;
        }
    }
}

// ---------------------------------------------------------------------------
// depthwise 3x3x3 conv: h2 = conv(h1) + conv_b  (validated in R1, unchanged)
// ---------------------------------------------------------------------------
__global__ __launch_bounds__(256) void conv_kernel(const float* __restrict__ cw,
                                                   const float* __restrict__ cb) {
    __shared__ uint32_t tile[10 * 16 * 16 * 4];
    const int tid = threadIdx.x;
    const int cc = blockIdx.x;  // channel chunk of 8
    const int bb = blockIdx.y;  // batch
    const uint32_t* h1w = (const uint32_t*)g_h1;

    for (int idx = tid; idx < 10 * 16 * 16 * 4; idx += 256) {
        int p = idx & 3;
        int sp = idx >> 2;
        int w = sp & 15, h = (sp >> 4) & 15, t = sp >> 8;
        int ts = t - 1, hs = h - 1, ws = w - 1;
        uint32_t v = 0;
        if ((unsigned)ts < 8u && (unsigned)hs < 14u && (unsigned)ws < 14u) {
            int row = (bb * 8 + ts) * 196 + hs * 14 + ws;
            v = h1w[(size_t)row * 192 + cc * 4 + p];
        }
        tile[idx] = v;
    }
    __syncthreads();

    const int p = tid & 3;
    const int c0 = cc * 8 + p * 2;
    float wx[27], wy[27];
#pragma unroll
    for (int i = 0; i < 27; i++) {
        wx[i] = cw[c0 * 27 + i];
        wy[i] = cw[(c0 + 1) * 27 + i];
    }
    const float bx = cb[c0], by = cb[c0 + 1];
    uint32_t* h2w = (uint32_t*)g_h2;

    for (int s = tid >> 2; s < 1568; s += 64) {
        int t = s / 196;
        int rem = s - t * 196;
        int h = rem / 14;
        int w = rem - h * 14;
        float ax = bx, ay = by;
#pragma unroll
        for (int dt = 0; dt < 3; dt++)
#pragma unroll
            for (int dh = 0; dh < 3; dh++)
#pragma unroll
                for (int dw = 0; dw < 3; dw++) {
                    uint32_t v = tile[(((t + dt) * 16 + (h + dh)) * 16 + (w + dw)) * 4 + p];
                    float lo = __uint_as_float(v << 16);
                    float hi = __uint_as_float(v & 0xffff0000u);
                    int wi = dt * 9 + dh * 3 + dw;
                    ax = fmaf(wx[wi], lo, ax);
                    ay = fmaf(wy[wi], hi, ay);
                }
        __nv_bfloat162 r = __floats2bfloat162_rn(ax, ay);
        int row = (bb * 8 + t) * 196 + h * 14 + w;
        h2w[(size_t)row * 192 + cc * 4 + p] = *(uint32_t*)&r;
    }
}

// ---------------------------------------------------------------------------
// fc2: out = h2 @ W2^T + b2 + x (residual), M=50176, N=768, K=384, fp32 out
// ---------------------------------------------------------------------------
__global__ __launch_bounds__(256) void fc2_kernel(const float* __restrict__ x,
                                                  const float* __restrict__ b2,
                                                  float* __restrict__ out) {
    __shared__ __align__(16) __nv_bfloat16 As[2 * STG];
    __shared__ __align__(16) __nv_bfloat16 Bs[2 * STG];
    const int bm = blockIdx.y * 128;
    const int bn = blockIdx.x * 128;
    float acc[2][8][4];
    gemm_loop<CAd>(g_h2, g_w2, As, Bs, bm, bn, acc);

    const int lane = threadIdx.x & 31, warp = threadIdx.x >> 5;
    const int wm = (warp & 3) * 32, wn = (warp >> 2) * 64;
    const int lane4 = lane & 3, laneg = lane >> 2;
#pragma unroll
    for (int i = 0; i < 2; i++) {
#pragma unroll
        for (int jj = 0; jj < 8; jj++) {
            int n = bn + wn + jj * 8 + lane4 * 2;
            float bx = b2[n], by = b2[n + 1];
            int m0 = bm + wm + i * 16 + laneg;
            int xr0 = m0 + m0 / 196 + 1;
            const float2 xv0 = *(const float2*)(x + (size_t)xr0 * CC + n);
            float2 o0;
            o0.x = acc[i][jj][0] + bx + xv0.x;
            o0.y = acc[i][jj][1] + by + xv0.y;
            *(float2*)(out + (size_t)xr0 * CC + n) = o0;
            int m1 = m0 + 8;
            int xr1 = m1 + m1 / 196 + 1;
            const float2 xv1 = *(const float2*)(x + (size_t)xr1 * CC + n);
            float2 o1;
            o1.x = acc[i][jj][2] + bx + xv1.x;
            o1.y = acc[i][jj][3] + by + xv1.y;
            *(float2*)(out + (size_t)xr1 * CC + n) = o1;
        }
    }
}

// ---------------------------------------------------------------------------
extern "C" void kernel_launch(void* const* d_in, const int* in_sizes, int n_in,
                              void* d_out, int out_size) {
    const float* x      = (const float*)d_in[0];
    const float* b1     = (const float*)d_in[2];
    const float* conv_w = (const float*)d_in[3];
    const float* conv_b = (const float*)d_in[4];
    const float* b2     = (const float*)d_in[6];
    const float* W1     = (const float*)d_in[1];
    const float* W2     = (const float*)d_in[5];
    float* out = (float*)d_out;

    prep_kernel<<<512, 256>>>(W1, W2, x, out);
    fc1_kernel<<<dim3(3, 392), 256>>>(b1);
    conv_kernel<<<dim3(48, 32), 256>>>(conv_w, conv_b);
    fc2_kernel<<<dim3(6, 392), 256>>>(x, b2, out);
}

// round 4
// speedup vs baseline: 1.0515x; 1.0515x over previous
#include <cuda_runtime.h>
#include <cuda_bf16.h>
#include <cstdint>

// Problem constants (fixed shapes)
#define B_   32
#define T_   8
#define LL   197
#define CC   768
#define CAd  384
#define BTd  256            // B_*T_
#define MM   50176          // BTd*196

// Scratch (device globals — no allocation allowed)
__device__ __align__(256) __nv_bfloat16 g_xb[(size_t)MM * CC];   // x without CLS, bf16
__device__ __align__(256) __nv_bfloat16 g_h1[(size_t)MM * CAd];
__device__ __align__(256) __nv_bfloat16 g_h2[(size_t)MM * CAd];
__device__ __align__(256) __nv_bfloat16 g_w1[CAd * CC];
__device__ __align__(256) __nv_bfloat16 g_w2[CC * CAd];

// ---------------------------------------------------------------------------
// prep: weights -> bf16, x(non-CLS) -> bf16 packed [MM, CC], copy CLS rows
// ---------------------------------------------------------------------------
__global__ void prep_kernel(const float* __restrict__ W1, const float* __restrict__ W2,
                            const float* __restrict__ x, float* __restrict__ out) {
    int stride = gridDim.x * blockDim.x;
    int i0 = blockIdx.x * blockDim.x + threadIdx.x;

    for (int i = i0; i < (CAd * CC) / 4; i += stride) {
        float4 v = ((const float4*)W1)[i];
        __nv_bfloat162 p0 = __floats2bfloat162_rn(v.x, v.y);
        __nv_bfloat162 p1 = __floats2bfloat162_rn(v.z, v.w);
        uint2 u; u.x = *(uint32_t*)&p0; u.y = *(uint32_t*)&p1;
        ((uint2*)g_w1)[i] = u;
    }
    for (int i = i0; i < (CAd * CC) / 4; i += stride) {
        float4 v = ((const float4*)W2)[i];
        __nv_bfloat162 p0 = __floats2bfloat162_rn(v.x, v.y);
        __nv_bfloat162 p1 = __floats2bfloat162_rn(v.z, v.w);
        uint2 u; u.x = *(uint32_t*)&p0; u.y = *(uint32_t*)&p1;
        ((uint2*)g_w2)[i] = u;
    }
    // x non-CLS tokens -> bf16 packed
    const int R4 = CC / 4;  // 192
    for (int i = i0; i < MM * R4; i += stride) {
        int m = i / R4;
        int c4 = i - m * R4;
        int xr = m + m / 196 + 1;
        float4 v = *(const float4*)(x + (size_t)xr * CC + c4 * 4);
        __nv_bfloat162 p0 = __floats2bfloat162_rn(v.x, v.y);
        __nv_bfloat162 p1 = __floats2bfloat162_rn(v.z, v.w);
        uint2 u; u.x = *(uint32_t*)&p0; u.y = *(uint32_t*)&p1;
        ((uint2*)g_xb)[(size_t)m * R4 + c4] = u;
    }
    // CLS rows copy x -> out
    for (int i = i0; i < (BTd * CC) / 4; i += stride) {
        int bt = i / (CC / 4), c4 = i - bt * (CC / 4);
        size_t off = (size_t)bt * LL * (CC / 4) + c4;
        ((float4*)out)[off] = ((const float4*)x)[off];
    }
}

// ---------------------------------------------------------------------------
// GEMM helpers (mma.sync m16n8k16 bf16 + cp.async staging)
// ---------------------------------------------------------------------------
__device__ __forceinline__ uint32_t smem_u32(const void* p) {
    return (uint32_t)__cvta_generic_to_shared(p);
}
__device__ __forceinline__ void ldm_x4(uint32_t* r, uint32_t addr) {
    asm volatile("ldmatrix.sync.aligned.m8n8.x4.shared.b16 {%0,%1,%2,%3}, [%4];\n"
                 : "=r"(r[0]), "=r"(r[1]), "=r"(r[2]), "=r"(r[3]) : "r"(addr));
}
__device__ __forceinline__ void mma_bf16(float* d, const uint32_t* a, uint32_t b0, uint32_t b1) {
    asm volatile(
        "mma.sync.aligned.m16n8k16.row.col.f32.bf16.bf16.f32 "
        "{%0,%1,%2,%3}, {%4,%5,%6,%7}, {%8,%9}, {%0,%1,%2,%3};\n"
        : "+f"(d[0]), "+f"(d[1]), "+f"(d[2]), "+f"(d[3])
        : "r"(a[0]), "r"(a[1]), "r"(a[2]), "r"(a[3]), "r"(b0), "r"(b1));
}
__device__ __forceinline__ void cp16(void* smem, const void* gmem) {
    uint32_t s = smem_u32(smem);
    asm volatile("cp.async.cg.shared.global [%0], [%1], 16;\n" :: "r"(s), "l"(gmem));
}
#define CP_COMMIT asm volatile("cp.async.commit_group;\n" ::: "memory")

#define SK 40           // smem row stride (32 + 8 pad) -> 80B, ldmatrix conflict-free
#define STGE (128 * SK) // elems per operand per stage (10240 B)
#define NBUF 4
#define GEMM_SMEM (NBUF * STGE * 2 * 2)   // 81920 B

// Shared GEMM mainloop: C[128x128] tile of A[M,K] * B[N,K]^T, both bf16 row-major.
// 4-stage cp.async pipeline, single barrier per k-tile, batched fragments.
// 8 warps as 4(M)x2(N), warp tile 32x64.
template<int K>
__device__ __forceinline__ void gemm_loop(const __nv_bfloat16* __restrict__ A,
                                          const __nv_bfloat16* __restrict__ B,
                                          __nv_bfloat16* As, __nv_bfloat16* Bs,
                                          int bm, int bn, float (&acc)[2][8][4]) {
    const int tid = threadIdx.x;
    const int row = tid >> 2;          // 0..63
    const int col = (tid & 3) * 8;     // 16B chunk offset
    const __nv_bfloat16* aptr[2] = {
        A + (size_t)(bm + row) * K + col,
        A + (size_t)(bm + row + 64) * K + col };
    const __nv_bfloat16* bptr[2] = {
        B + (size_t)(bn + row) * K + col,
        B + (size_t)(bn + row + 64) * K + col };

    const int lane = tid & 31, warp = tid >> 5;
    const int wm = (warp & 3) * 32, wn = (warp >> 2) * 64;
    const int lr = ((lane >> 3) & 1) * 8 + (lane & 7);
    const int kc = (lane >> 4) * 8;

#pragma unroll
    for (int i = 0; i < 2; i++)
#pragma unroll
        for (int j = 0; j < 8; j++)
#pragma unroll
            for (int c = 0; c < 4; c++) acc[i][j][c] = 0.f;

    auto load_stage = [&](int st, int buf) {
        const int k0 = st * 32;
        __nv_bfloat16* Ad = As + buf * STGE;
        __nv_bfloat16* Bd = Bs + buf * STGE;
#pragma unroll
        for (int p = 0; p < 2; p++) {
            cp16(&Ad[(row + p * 64) * SK + col], aptr[p] + k0);
            cp16(&Bd[(row + p * 64) * SK + col], bptr[p] + k0);
        }
    };

    load_stage(0, 0); CP_COMMIT;
    load_stage(1, 1); CP_COMMIT;
    load_stage(2, 2); CP_COMMIT;

    const int nk = K / 32;
    int cb = 0, lb = 3;
#pragma unroll 1
    for (int kt = 0; kt < nk; kt++) {
        asm volatile("cp.async.wait_group 2;\n" ::: "memory");
        __syncthreads();    // all warps past compute kt-1; buffer lb=(kt-1)%4 free
        if (kt + 3 < nk) load_stage(kt + 3, lb);
        CP_COMMIT;

        uint32_t a_s = smem_u32(As + cb * STGE);
        uint32_t b_s = smem_u32(Bs + cb * STGE);
        uint32_t ra[2][2][4], rb[2][4][4];
#pragma unroll
        for (int h = 0; h < 2; h++) {
            const int ks = h * 16;
#pragma unroll
            for (int i = 0; i < 2; i++)
                ldm_x4(ra[h][i], a_s + (uint32_t)(((wm + i * 16 + lr) * SK + ks + kc) * 2));
#pragma unroll
            for (int j = 0; j < 4; j++)
                ldm_x4(rb[h][j], b_s + (uint32_t)(((wn + j * 16 + lr) * SK + ks + kc) * 2));
        }
#pragma unroll
        for (int h = 0; h < 2; h++)
#pragma unroll
            for (int i = 0; i < 2; i++)
#pragma unroll
                for (int j = 0; j < 4; j++) {
                    mma_bf16(acc[i][2 * j],     ra[h][i], rb[h][j][0], rb[h][j][2]);
                    mma_bf16(acc[i][2 * j + 1], ra[h][i], rb[h][j][1], rb[h][j][3]);
                }
        cb = (cb + 1) & 3;
        lb = (lb + 1) & 3;
    }
}

// ---------------------------------------------------------------------------
// fc1: h1 = xb @ W1^T + b1   (M=50176, N=384, K=768), out bf16
// ---------------------------------------------------------------------------
__global__ __launch_bounds__(256) void fc1_kernel(const float* __restrict__ b1) {
    extern __shared__ __align__(16) __nv_bfloat16 smem[];
    __nv_bfloat16* As = smem;
    __nv_bfloat16* Bs = smem + NBUF * STGE;
    const int bm = blockIdx.y * 128;
    const int bn = blockIdx.x * 128;
    float acc[2][8][4];
    gemm_loop<CC>(g_xb, g_w1, As, Bs, bm, bn, acc);

    const int lane = threadIdx.x & 31, warp = threadIdx.x >> 5;
    const int wm = (warp & 3) * 32, wn = (warp >> 2) * 64;
    const int lane4 = lane & 3, laneg = lane >> 2;
    uint32_t* h1w = (uint32_t*)g_h1;
#pragma unroll
    for (int i = 0; i < 2; i++) {
#pragma unroll
        for (int jj = 0; jj < 8; jj++) {
            int n = bn + wn + jj * 8 + lane4 * 2;
            float bx = b1[n], by = b1[n + 1];
            int m0 = bm + wm + i * 16 + laneg;
            __nv_bfloat162 v0 = __floats2bfloat162_rn(acc[i][jj][0] + bx, acc[i][jj][1] + by);
            h1w[(size_t)m0 * (CAd / 2) + (n >> 1)] = *(uint32_t*)&v0;
            __nv_bfloat162 v1 = __floats2bfloat162_rn(acc[i][jj][2] + bx, acc[i][jj][3] + by);
            h1w[(size_t)(m0 + 8) * (CAd / 2) + (n >> 1)] = *(uint32_t*)&v1;
        }
    }
}

// ---------------------------------------------------------------------------
// depthwise 3x3x3 conv: h2 = conv(h1) + conv_b  (validated; unchanged)
// ---------------------------------------------------------------------------
__global__ __launch_bounds__(256) void conv_kernel(const float* __restrict__ cw,
                                                   const float* __restrict__ cb) {
    __shared__ uint32_t tile[10 * 16 * 16 * 4];
    const int tid = threadIdx.x;
    const int cc = blockIdx.x;
    const int bb = blockIdx.y;
    const uint32_t* h1w = (const uint32_t*)g_h1;

    for (int idx = tid; idx < 10 * 16 * 16 * 4; idx += 256) {
        int p = idx & 3;
        int sp = idx >> 2;
        int w = sp & 15, h = (sp >> 4) & 15, t = sp >> 8;
        int ts = t - 1, hs = h - 1, ws = w - 1;
        uint32_t v = 0;
        if ((unsigned)ts < 8u && (unsigned)hs < 14u && (unsigned)ws < 14u) {
            int row = (bb * 8 + ts) * 196 + hs * 14 + ws;
            v = h1w[(size_t)row * 192 + cc * 4 + p];
        }
        tile[idx] = v;
    }
    __syncthreads();

    const int p = tid & 3;
    const int c0 = cc * 8 + p * 2;
    float wx[27], wy[27];
#pragma unroll
    for (int i = 0; i < 27; i++) {
        wx[i] = cw[c0 * 27 + i];
        wy[i] = cw[(c0 + 1) * 27 + i];
    }
    const float bx = cb[c0], by = cb[c0 + 1];
    uint32_t* h2w = (uint32_t*)g_h2;

    for (int s = tid >> 2; s < 1568; s += 64) {
        int t = s / 196;
        int rem = s - t * 196;
        int h = rem / 14;
        int w = rem - h * 14;
        float ax = bx, ay = by;
#pragma unroll
        for (int dt = 0; dt < 3; dt++)
#pragma unroll
            for (int dh = 0; dh < 3; dh++)
#pragma unroll
                for (int dw = 0; dw < 3; dw++) {
                    uint32_t v = tile[(((t + dt) * 16 + (h + dh)) * 16 + (w + dw)) * 4 + p];
                    float lo = __uint_as_float(v << 16);
                    float hi = __uint_as_float(v & 0xffff0000u);
                    int wi = dt * 9 + dh * 3 + dw;
                    ax = fmaf(wx[wi], lo, ax);
                    ay = fmaf(wy[wi], hi, ay);
                }
        __nv_bfloat162 r = __floats2bfloat162_rn(ax, ay);
        int row = (bb * 8 + t) * 196 + h * 14 + w;
        h2w[(size_t)row * 192 + cc * 4 + p] = *(uint32_t*)&r;
    }
}

// ---------------------------------------------------------------------------
// fc2: out = h2 @ W2^T + b2 + x (residual), M=50176, N=768, K=384, fp32 out
// ---------------------------------------------------------------------------
__global__ __launch_bounds__(256) void fc2_kernel(const float* __restrict__ x,
                                                  const float* __restrict__ b2,
                                                  float* __restrict__ out) {
    extern __shared__ __align__(16) __nv_bfloat16 smem[];
    __nv_bfloat16* As = smem;
    __nv_bfloat16* Bs = smem + NBUF * STGE;
    const int bm = blockIdx.y * 128;
    const int bn = blockIdx.x * 128;
    float acc[2][8][4];
    gemm_loop<CAd>(g_h2, g_w2, As, Bs, bm, bn, acc);

    const int lane = threadIdx.x & 31, warp = threadIdx.x >> 5;
    const int wm = (warp & 3) * 32, wn = (warp >> 2) * 64;
    const int lane4 = lane & 3, laneg = lane >> 2;
#pragma unroll
    for (int i = 0; i < 2; i++) {
#pragma unroll
        for (int jj = 0; jj < 8; jj++) {
            int n = bn + wn + jj * 8 + lane4 * 2;
            float bx = b2[n], by = b2[n + 1];
            int m0 = bm + wm + i * 16 + laneg;
            int xr0 = m0 + m0 / 196 + 1;
            const float2 xv0 = *(const float2*)(x + (size_t)xr0 * CC + n);
            float2 o0;
            o0.x = acc[i][jj][0] + bx + xv0.x;
            o0.y = acc[i][jj][1] + by + xv0.y;
            *(float2*)(out + (size_t)xr0 * CC + n) = o0;
            int m1 = m0 + 8;
            int xr1 = m1 + m1 / 196 + 1;
            const float2 xv1 = *(const float2*)(x + (size_t)xr1 * CC + n);
            float2 o1;
            o1.x = acc[i][jj][2] + bx + xv1.x;
            o1.y = acc[i][jj][3] + by + xv1.y;
            *(float2*)(out + (size_t)xr1 * CC + n) = o1;
        }
    }
}

// ---------------------------------------------------------------------------
extern "C" void kernel_launch(void* const* d_in, const int* in_sizes, int n_in,
                              void* d_out, int out_size) {
    const float* x      = (const float*)d_in[0];
    const float* W1     = (const float*)d_in[1];
    const float* b1     = (const float*)d_in[2];
    const float* conv_w = (const float*)d_in[3];
    const float* conv_b = (const float*)d_in[4];
    const float* W2     = (const float*)d_in[5];
    const float* b2     = (const float*)d_in[6];
    float* out = (float*)d_out;

    cudaFuncSetAttribute(fc1_kernel, cudaFuncAttributeMaxDynamicSharedMemorySize, GEMM_SMEM);
    cudaFuncSetAttribute(fc2_kernel, cudaFuncAttributeMaxDynamicSharedMemorySize, GEMM_SMEM);

    prep_kernel<<<512, 256>>>(W1, W2, x, out);
    fc1_kernel<<<dim3(3, 392), 256, GEMM_SMEM>>>(b1);
    conv_kernel<<<dim3(48, 32), 256>>>(conv_w, conv_b);
    fc2_kernel<<<dim3(6, 392), 256, GEMM_SMEM>>>(x, b2, out);
}